// round 17
// baseline (speedup 1.0000x reference)
#include <cuda_runtime.h>
#include <cuda_bf16.h>
#include <math.h>
#include <stdint.h>

#define BATCH 4
#define NPTS 20000
#define NS 1024
#define NC 128
#define NK 32
#define NREF (BATCH * NS)   // 4096
#define NSM 148

// ---------------- scratch (static device globals; no allocations) ----------------
__device__ int   g_idx[NREF * NK];                                   // 512 KB
// x2 in FRAGMENT-MAJOR layout: [group g][mb 0..7][ks 0..7][lane 0..31][4 u32]
__device__ __align__(16) uint32_t g_x2fhi[(size_t)1024 * 8192];
__device__ __align__(16) uint32_t g_x2flo[(size_t)1024 * 8192];
// pre-converted weights (hi/lo bf16, n-major, padded/zero-filled K)
__device__ __align__(16) __nv_bfloat16 g_b1hi[64 * 152], g_b1lo[64 * 152];
__device__ __align__(16) __nv_bfloat16 g_b2hi[128 * 72], g_b2lo[128 * 72];
__device__ __align__(16) __nv_bfloat16 g_w3hi[256 * 136], g_w3lo[256 * 136];
__device__ float g_sc1[64], g_sh1[64], g_sc2[128], g_sh2[128], g_sc3[256], g_sh3[256];

__device__ __forceinline__ void split_bf(float v, __nv_bfloat16& h, __nv_bfloat16& l) {
    h = __float2bfloat16_rn(v);
    l = __float2bfloat16_rn(v - __bfloat162float(h));
}
__device__ __forceinline__ uint32_t pack_bf2(__nv_bfloat16 a, __nv_bfloat16 b) {
    uint16_t ua = *(uint16_t*)&a, ub = *(uint16_t*)&b;
    return (uint32_t)ua | ((uint32_t)ub << 16);
}
__device__ __forceinline__ void pack_hl2(float a, float b, uint32_t& hi, uint32_t& lo) {
    __nv_bfloat16 ha, la, hb, lb;
    split_bf(a, ha, la); split_bf(b, hb, lb);
    hi = pack_bf2(ha, hb); lo = pack_bf2(la, lb);
}
__device__ __forceinline__ void mma_bf16(float* d, const uint32_t* a, const uint32_t* b) {
    asm volatile(
        "mma.sync.aligned.m16n8k16.row.col.f32.bf16.bf16.f32 "
        "{%0,%1,%2,%3}, {%4,%5,%6,%7}, {%8,%9}, {%0,%1,%2,%3};"
        : "+f"(d[0]), "+f"(d[1]), "+f"(d[2]), "+f"(d[3])
        : "r"(a[0]), "r"(a[1]), "r"(a[2]), "r"(a[3]), "r"(b[0]), "r"(b[1]));
}
__device__ __forceinline__ void ldsm_x4(uint32_t* r, uint32_t addr) {
    asm volatile("ldmatrix.sync.aligned.m8n8.x4.shared.b16 {%0,%1,%2,%3}, [%4];"
                 : "=r"(r[0]), "=r"(r[1]), "=r"(r[2]), "=r"(r[3]) : "r"(addr));
}

// =====================================================================
// Kernel 0: prep — convert weights + BN coeffs once per launch.
// =====================================================================
__global__ __launch_bounds__(256) void prep_kernel(
    const float* __restrict__ W1, const float* __restrict__ W2, const float* __restrict__ W3,
    const float* __restrict__ g1, const float* __restrict__ b1,
    const float* __restrict__ m1, const float* __restrict__ v1,
    const float* __restrict__ g2, const float* __restrict__ b2,
    const float* __restrict__ m2, const float* __restrict__ v2,
    const float* __restrict__ g3, const float* __restrict__ b3,
    const float* __restrict__ m3, const float* __restrict__ v3)
{
    int tid = blockIdx.x * 256 + threadIdx.x;
    int stride = gridDim.x * 256;
    for (int i = tid; i < 64 * 152; i += stride) {
        int n = i / 152, k = i - n * 152;
        float wv = (k < 131) ? W1[k * 64 + n] : 0.0f;
        __nv_bfloat16 h, l; split_bf(wv, h, l);
        g_b1hi[i] = h; g_b1lo[i] = l;
    }
    for (int i = tid; i < 128 * 72; i += stride) {
        int n = i / 72, k = i - n * 72;
        float wv = (k < 64) ? W2[k * 128 + n] : 0.0f;
        __nv_bfloat16 h, l; split_bf(wv, h, l);
        g_b2hi[i] = h; g_b2lo[i] = l;
    }
    for (int i = tid; i < 256 * 136; i += stride) {
        int n = i / 136, k = i - n * 136;
        float wv = (k < 128) ? W3[k * 256 + n] : 0.0f;
        __nv_bfloat16 h, l; split_bf(wv, h, l);
        g_w3hi[i] = h; g_w3lo[i] = l;
    }
    if (tid < 64) {
        float s = g1[tid] * rsqrtf(v1[tid] + 1e-5f);
        g_sc1[tid] = s; g_sh1[tid] = b1[tid] - m1[tid] * s;
    } else if (tid < 192) {
        int j = tid - 64;
        float s = g2[j] * rsqrtf(v2[j] + 1e-5f);
        g_sc2[j] = s; g_sh2[j] = b2[j] - m2[j] * s;
    } else if (tid < 448) {
        int j = tid - 192;
        float s = g3[j] * rsqrtf(v3[j] + 1e-5f);
        g_sc3[j] = s; g_sh3[j] = b3[j] - m3[j] * s;
    }
}

// =====================================================================
// Kernel 1: ball query (R16 version; 256 pts/iter).
// =====================================================================
__global__ __launch_bounds__(256) void ball_query_kernel(
    const float* __restrict__ points, const float* __restrict__ refs)
{
    int warp = (blockIdx.x * 256 + threadIdx.x) >> 5;
    int lane = threadIdx.x & 31;
    if (warp >= NREF) return;
    int b = warp >> 10;
    const float* rp = refs + (size_t)warp * 3;
    float rx = rp[0], ry = rp[1], rz = rp[2];
    float rr2 = rx * rx + ry * ry + rz * rz;
    const float R2 = 0.2f * 0.2f;
    int* out = g_idx + warp * NK;
    const float* pbase = points + (size_t)b * NPTS * 3;

    int count = 0;
    int first = -1;
    for (int base = 0; base < NPTS && count < NK; base += 256) {
        float px[8], py[8], pz[8];
        #pragma unroll
        for (int j = 0; j < 8; j++) {
            int i = base + j * 32 + lane;
            bool valid = (i < NPTS);
            int ii = valid ? i : 0;
            px[j] = pbase[ii * 3 + 0];
            py[j] = pbase[ii * 3 + 1];
            pz[j] = pbase[ii * 3 + 2];
            if (!valid) { px[j] = 1e9f; }
        }
        #pragma unroll
        for (int j = 0; j < 8; j++) {
            int i = base + j * 32 + lane;
            float pp2 = px[j] * px[j] + py[j] * py[j] + pz[j] * pz[j];
            float dot = rx * px[j] + ry * py[j] + rz * pz[j];
            float d2 = rr2 + pp2 - 2.0f * dot;
            bool pred = d2 < R2;
            unsigned m = __ballot_sync(0xffffffffu, pred);
            if (m) {
                if (first < 0) first = __shfl_sync(0xffffffffu, i, __ffs(m) - 1);
                if (pred) {
                    int rank = __popc(m & ((1u << lane) - 1u));
                    int slot = count + rank;
                    if (slot < NK) out[slot] = i;
                }
                count += __popc(m);
            }
        }
    }
    if (count < NK) {
        int fill = (count == 0) ? (NPTS - 1) : first;
        if (lane >= count) out[lane] = fill;
    }
}

// =====================================================================
// Kernel 2: PERSISTENT fused layer1+layer2. 296 CTAs; weights staged once.
// =====================================================================
#define B1_STR 152
#define B2_STR 72
#define SB12_B1HI 0
#define SB12_B1LO (SB12_B1HI + 64*B1_STR*2)
#define SB12_B2HI (SB12_B1LO + 64*B1_STR*2)
#define SB12_B2LO (SB12_B2HI + 128*B2_STR*2)
#define SB12_SC1  (SB12_B2LO + 128*B2_STR*2)
#define SB12_SH1  (SB12_SC1 + 64*4)
#define SB12_SC2  (SB12_SH1 + 64*4)
#define SB12_SH2  (SB12_SC2 + 128*4)
#define SB12_TOT  (SB12_SH2 + 128*4)           // 77312

__global__ __launch_bounds__(256, 2) void mlp12_mma_kernel(
    const float* __restrict__ points, const float* __restrict__ features,
    const float* __restrict__ refs)
{
    extern __shared__ char smc[];
    __nv_bfloat16* B1hi = (__nv_bfloat16*)(smc + SB12_B1HI);
    __nv_bfloat16* B1lo = (__nv_bfloat16*)(smc + SB12_B1LO);
    __nv_bfloat16* B2hi = (__nv_bfloat16*)(smc + SB12_B2HI);
    __nv_bfloat16* B2lo = (__nv_bfloat16*)(smc + SB12_B2LO);
    float* sc1s = (float*)(smc + SB12_SC1);
    float* sh1s = (float*)(smc + SB12_SH1);
    float* sc2s = (float*)(smc + SB12_SC2);
    float* sh2s = (float*)(smc + SB12_SH2);

    int t = threadIdx.x;
    int lane = t & 31, w = t >> 5;

    {
        uint4* d1h = (uint4*)B1hi; const uint4* s1h = (const uint4*)g_b1hi;
        uint4* d1l = (uint4*)B1lo; const uint4* s1l = (const uint4*)g_b1lo;
        for (int e = t; e < 1216; e += 256) { d1h[e] = s1h[e]; d1l[e] = s1l[e]; }
        uint4* d2h = (uint4*)B2hi; const uint4* s2h = (const uint4*)g_b2hi;
        uint4* d2l = (uint4*)B2lo; const uint4* s2l = (const uint4*)g_b2lo;
        for (int e = t; e < 1152; e += 256) { d2h[e] = s2h[e]; d2l[e] = s2l[e]; }
        if (t < 64) { sc1s[t] = g_sc1[t]; sh1s[t] = g_sh1[t]; }
        if (t < 128) { sc2s[t] = g_sc2[t]; sh2s[t] = g_sh2[t]; }
    }
    __syncthreads();

    int rl = lane >> 2;           // 0..7
    int cl = (lane & 3) * 2;      // 0,2,4,6
    int q = w >> 1;

    for (int g = blockIdx.x; g < 1024; g += 2 * NSM) {
        int ref0 = g * 4;
        int b = ref0 >> 10;
        int ridx = ref0 + q;
        int rA = 16 * w + rl;
        int rB = rA + 8;
        int pidA = g_idx[ridx * NK + (rA & 31)];
        int pidB = g_idx[ridx * NK + (rB & 31)];
        const float* fA = features + ((size_t)b * NPTS + pidA) * 128;
        const float* fB = features + ((size_t)b * NPTS + pidB) * 128;
        float pA0, pA1, pA2, pB0, pB1, pB2;
        {
            const float* pa = points + ((size_t)b * NPTS + pidA) * 3;
            const float* pb = points + ((size_t)b * NPTS + pidB) * 3;
            const float* rr = refs + (size_t)ridx * 3;
            float r0v = rr[0], r1v = rr[1], r2v = rr[2];
            pA0 = (pa[0] - r0v) * 5.0f; pA1 = (pa[1] - r1v) * 5.0f; pA2 = (pa[2] - r2v) * 5.0f;
            pB0 = (pb[0] - r0v) * 5.0f; pB1 = (pb[1] - r1v) * 5.0f; pB2 = (pb[2] - r2v) * 5.0f;
        }

        float d1[8][4];
        #pragma unroll
        for (int ni = 0; ni < 8; ni++)
            #pragma unroll
            for (int e = 0; e < 4; e++) d1[ni][e] = 0.0f;

        #pragma unroll
        for (int ks = 0; ks < 9; ks++) {
            int c = 16 * ks + cl;
            float vA0, vA1, vA8, vA9, vB0v, vB1v, vB8, vB9;
            if (ks == 0) {
                if (cl == 0)      { vA0 = pA0;      vA1 = pA1;      vB0v = pB0;      vB1v = pB1; }
                else if (cl == 2) { vA0 = pA2;      vA1 = fA[0];    vB0v = pB2;      vB1v = fB[0]; }
                else              { vA0 = fA[cl-3]; vA1 = fA[cl-2]; vB0v = fB[cl-3]; vB1v = fB[cl-2]; }
                vA8 = fA[cl + 5]; vA9 = fA[cl + 6];
                vB8 = fB[cl + 5]; vB9 = fB[cl + 6];
            } else if (ks == 8) {
                if (cl == 0)      { vA0 = fA[125]; vA1 = fA[126]; vB0v = fB[125]; vB1v = fB[126]; }
                else if (cl == 2) { vA0 = fA[127]; vA1 = 0.0f;    vB0v = fB[127]; vB1v = 0.0f; }
                else              { vA0 = 0.0f;    vA1 = 0.0f;    vB0v = 0.0f;    vB1v = 0.0f; }
                vA8 = 0.0f; vA9 = 0.0f; vB8 = 0.0f; vB9 = 0.0f;
            } else {
                vA0 = fA[c - 3]; vA1 = fA[c - 2]; vA8 = fA[c + 5]; vA9 = fA[c + 6];
                vB0v = fB[c - 3]; vB1v = fB[c - 2]; vB8 = fB[c + 5]; vB9 = fB[c + 6];
            }
            uint32_t ahi[4], alo[4];
            pack_hl2(vA0, vA1, ahi[0], alo[0]);
            pack_hl2(vB0v, vB1v, ahi[1], alo[1]);
            pack_hl2(vA8, vA9, ahi[2], alo[2]);
            pack_hl2(vB8, vB9, ahi[3], alo[3]);

            int k0 = 16 * ks;
            uint32_t bh[8][2], bl[8][2];
            #pragma unroll
            for (int ni = 0; ni < 8; ni++) {
                int n = ni * 8 + rl, k = k0 + cl;
                bh[ni][0] = *(const uint32_t*)&B1hi[n * B1_STR + k];
                bh[ni][1] = *(const uint32_t*)&B1hi[n * B1_STR + k + 8];
                bl[ni][0] = *(const uint32_t*)&B1lo[n * B1_STR + k];
                bl[ni][1] = *(const uint32_t*)&B1lo[n * B1_STR + k + 8];
            }
            #pragma unroll
            for (int ni = 0; ni < 8; ni++) mma_bf16(d1[ni], ahi, bh[ni]);
            #pragma unroll
            for (int ni = 0; ni < 8; ni++) mma_bf16(d1[ni], ahi, bl[ni]);
            #pragma unroll
            for (int ni = 0; ni < 8; ni++) mma_bf16(d1[ni], alo, bh[ni]);
        }

        uint32_t a2hi[4][4], a2lo[4][4];
        #pragma unroll
        for (int kb = 0; kb < 4; kb++) {
            int colL = 16 * kb + cl;
            int colR = colL + 8;
            float sL0 = sc1s[colL], hL0 = sh1s[colL], sL1 = sc1s[colL + 1], hL1 = sh1s[colL + 1];
            float sR0 = sc1s[colR], hR0 = sh1s[colR], sR1 = sc1s[colR + 1], hR1 = sh1s[colR + 1];
            float y0 = fmaxf(fmaf(d1[2 * kb][0], sL0, hL0), 0.0f);
            float y1 = fmaxf(fmaf(d1[2 * kb][1], sL1, hL1), 0.0f);
            float y2 = fmaxf(fmaf(d1[2 * kb][2], sL0, hL0), 0.0f);
            float y3 = fmaxf(fmaf(d1[2 * kb][3], sL1, hL1), 0.0f);
            float u0 = fmaxf(fmaf(d1[2 * kb + 1][0], sR0, hR0), 0.0f);
            float u1 = fmaxf(fmaf(d1[2 * kb + 1][1], sR1, hR1), 0.0f);
            float u2 = fmaxf(fmaf(d1[2 * kb + 1][2], sR0, hR0), 0.0f);
            float u3 = fmaxf(fmaf(d1[2 * kb + 1][3], sR1, hR1), 0.0f);
            pack_hl2(y0, y1, a2hi[kb][0], a2lo[kb][0]);
            pack_hl2(y2, y3, a2hi[kb][1], a2lo[kb][1]);
            pack_hl2(u0, u1, a2hi[kb][2], a2lo[kb][2]);
            pack_hl2(u2, u3, a2hi[kb][3], a2lo[kb][3]);
        }

        #pragma unroll
        for (int h = 0; h < 2; h++) {
            float d2[8][4];
            #pragma unroll
            for (int ni = 0; ni < 8; ni++)
                #pragma unroll
                for (int e = 0; e < 4; e++) d2[ni][e] = 0.0f;

            #pragma unroll
            for (int ks = 0; ks < 4; ks++) {
                int k = 16 * ks + cl;
                uint32_t bh[8][2], bl[8][2];
                #pragma unroll
                for (int ni = 0; ni < 8; ni++) {
                    int n = 64 * h + ni * 8 + rl;
                    bh[ni][0] = *(const uint32_t*)&B2hi[n * B2_STR + k];
                    bh[ni][1] = *(const uint32_t*)&B2hi[n * B2_STR + k + 8];
                    bl[ni][0] = *(const uint32_t*)&B2lo[n * B2_STR + k];
                    bl[ni][1] = *(const uint32_t*)&B2lo[n * B2_STR + k + 8];
                }
                #pragma unroll
                for (int ni = 0; ni < 8; ni++) mma_bf16(d2[ni], a2hi[ks], bh[ni]);
                #pragma unroll
                for (int ni = 0; ni < 8; ni++) mma_bf16(d2[ni], a2hi[ks], bl[ni]);
                #pragma unroll
                for (int ni = 0; ni < 8; ni++) mma_bf16(d2[ni], a2lo[ks], bh[ni]);
            }
            #pragma unroll
            for (int kp = 0; kp < 4; kp++) {
                int ni0 = 2 * kp, ni1 = 2 * kp + 1;
                int col0 = 64 * h + ni0 * 8 + cl;
                int col1 = 64 * h + ni1 * 8 + cl;
                float s00 = sc2s[col0], h00 = sh2s[col0], s01 = sc2s[col0 + 1], h01 = sh2s[col0 + 1];
                float s10 = sc2s[col1], h10 = sh2s[col1], s11 = sc2s[col1 + 1], h11 = sh2s[col1 + 1];
                float yA0 = fmaxf(fmaf(d2[ni0][0], s00, h00), 0.0f);
                float yA1 = fmaxf(fmaf(d2[ni0][1], s01, h01), 0.0f);
                float yB0 = fmaxf(fmaf(d2[ni0][2], s00, h00), 0.0f);
                float yB1 = fmaxf(fmaf(d2[ni0][3], s01, h01), 0.0f);
                float zA0 = fmaxf(fmaf(d2[ni1][0], s10, h10), 0.0f);
                float zA1 = fmaxf(fmaf(d2[ni1][1], s11, h11), 0.0f);
                float zB0 = fmaxf(fmaf(d2[ni1][2], s10, h10), 0.0f);
                float zB1 = fmaxf(fmaf(d2[ni1][3], s11, h11), 0.0f);
                uint32_t r0h, r0l, r1h, r1l, r2h, r2l, r3h, r3l;
                pack_hl2(yA0, yA1, r0h, r0l);
                pack_hl2(yB0, yB1, r1h, r1l);
                pack_hl2(zA0, zA1, r2h, r2l);
                pack_hl2(zB0, zB1, r3h, r3l);
                int ks_t = 4 * h + kp;
                size_t base = ((((size_t)g * 8 + w) * 8) + ks_t) * 128 + lane * 4;
                *(uint4*)&g_x2fhi[base] = make_uint4(r0h, r1h, r2h, r3h);
                *(uint4*)&g_x2flo[base] = make_uint4(r0l, r1l, r2l, r3l);
            }
        }
    }
}

// =====================================================================
// Kernel 3: PERSISTENT layer3 — 296 CTAs; B staged once per CTA;
// loop over groups. A via LDG.128 fragment-major; B via ldmatrix.x4.
// =====================================================================
#define BF_STRIDE 136
#define S3B_BHI 0
#define S3B_BLO (S3B_BHI + 128*BF_STRIDE*2)    // 34816
#define S3B_SC  (S3B_BLO + 128*BF_STRIDE*2)    // 69632
#define S3B_SH  (S3B_SC + 128*4)               // 70144
#define S3B_TOTAL (S3B_SH + 128*4)             // 70656

__global__ __launch_bounds__(256, 2) void mlp3_mma_kernel(float* __restrict__ out)
{
    extern __shared__ char smc[];
    __nv_bfloat16* Bhi = (__nv_bfloat16*)(smc + S3B_BHI);
    __nv_bfloat16* Blo = (__nv_bfloat16*)(smc + S3B_BLO);
    float* scs = (float*)(smc + S3B_SC);
    float* shs = (float*)(smc + S3B_SH);

    int t = threadIdx.x;
    int lane = t & 31, wid = t >> 5;
    int colhalf = blockIdx.x & 1;
    int work0 = blockIdx.x >> 1;          // 0..147
    int colbase = colhalf * 128;

    if (t < 128) {
        scs[t] = g_sc3[colbase + t];
        shs[t] = g_sh3[colbase + t];
    }
    {
        const uint4* sh4 = (const uint4*)g_w3hi + colbase * 17;
        const uint4* sl4 = (const uint4*)g_w3lo + colbase * 17;
        uint4* dh4 = (uint4*)Bhi;
        uint4* dl4 = (uint4*)Blo;
        for (int e = t; e < 128 * 17; e += 256) {
            dh4[e] = sh4[e];
            dl4[e] = sl4[e];
        }
    }
    __syncthreads();

    int c0 = (wid & 1) * 64;
    int q  = wid >> 1;
    int rl = lane >> 2;
    int cl = (lane & 3) * 2;

    uint32_t bhAddr[4], blAddr[4];
    {
        int group = lane >> 3, r = lane & 7;
        int koff = 8 * (group & 1);
        int nofs = 8 * (group >> 1) + r;
        #pragma unroll
        for (int np = 0; np < 4; np++) {
            int n = c0 + 16 * np + nofs;
            uint32_t off = (uint32_t)(n * BF_STRIDE + koff) * 2;
            bhAddr[np] = (uint32_t)__cvta_generic_to_shared(Bhi) + off;
            blAddr[np] = (uint32_t)__cvta_generic_to_shared(Blo) + off;
        }
    }

    for (int g = work0; g < 1024; g += NSM) {
        float d[2][8][4];
        #pragma unroll
        for (int mi = 0; mi < 2; mi++)
            #pragma unroll
            for (int ni = 0; ni < 8; ni++)
                #pragma unroll
                for (int e = 0; e < 4; e++) d[mi][ni][e] = 0.0f;

        const uint32_t* Afh = g_x2fhi + (size_t)g * 8192 + (size_t)(2 * q) * 1024 + lane * 4;
        const uint32_t* Afl = g_x2flo + (size_t)g * 8192 + (size_t)(2 * q) * 1024 + lane * 4;

        for (int ks = 0; ks < 8; ks++) {
            uint32_t ahi[2][4], alo[2][4];
            #pragma unroll
            for (int mi = 0; mi < 2; mi++) {
                uint4 vh = *(const uint4*)(Afh + (size_t)mi * 1024 + ks * 128);
                uint4 vl = *(const uint4*)(Afl + (size_t)mi * 1024 + ks * 128);
                ahi[mi][0] = vh.x; ahi[mi][1] = vh.y; ahi[mi][2] = vh.z; ahi[mi][3] = vh.w;
                alo[mi][0] = vl.x; alo[mi][1] = vl.y; alo[mi][2] = vl.z; alo[mi][3] = vl.w;
            }
            uint32_t bhi[8][2], blo[8][2];
            uint32_t kbyte = (uint32_t)(ks * 16) * 2;
            #pragma unroll
            for (int np = 0; np < 4; np++) {
                uint32_t rh[4], rlv[4];
                ldsm_x4(rh, bhAddr[np] + kbyte);
                ldsm_x4(rlv, blAddr[np] + kbyte);
                bhi[2 * np][0] = rh[0]; bhi[2 * np][1] = rh[1];
                bhi[2 * np + 1][0] = rh[2]; bhi[2 * np + 1][1] = rh[3];
                blo[2 * np][0] = rlv[0]; blo[2 * np][1] = rlv[1];
                blo[2 * np + 1][0] = rlv[2]; blo[2 * np + 1][1] = rlv[3];
            }
            #pragma unroll
            for (int mi = 0; mi < 2; mi++)
                #pragma unroll
                for (int ni = 0; ni < 8; ni++) mma_bf16(d[mi][ni], ahi[mi], bhi[ni]);
            #pragma unroll
            for (int mi = 0; mi < 2; mi++)
                #pragma unroll
                for (int ni = 0; ni < 8; ni++) mma_bf16(d[mi][ni], ahi[mi], blo[ni]);
            #pragma unroll
            for (int mi = 0; mi < 2; mi++)
                #pragma unroll
                for (int ni = 0; ni < 8; ni++) mma_bf16(d[mi][ni], alo[mi], bhi[ni]);
        }

        #pragma unroll
        for (int ni = 0; ni < 8; ni++) {
            #pragma unroll
            for (int e = 0; e < 2; e++) {
                int col = c0 + ni * 8 + cl + e;
                float s = scs[col], h = shs[col];
                float mx = 0.0f;
                #pragma unroll
                for (int mi = 0; mi < 2; mi++) {
                    mx = fmaxf(mx, fmaxf(fmaf(d[mi][ni][e],     s, h), 0.0f));
                    mx = fmaxf(mx, fmaxf(fmaf(d[mi][ni][2 + e], s, h), 0.0f));
                }
                mx = fmaxf(mx, __shfl_xor_sync(0xffffffffu, mx, 4));
                mx = fmaxf(mx, __shfl_xor_sync(0xffffffffu, mx, 8));
                mx = fmaxf(mx, __shfl_xor_sync(0xffffffffu, mx, 16));
                if (lane < 4)
                    out[((size_t)g * 4 + q) * 256 + colbase + col] = mx;
            }
        }
    }
}

// =====================================================================
extern "C" void kernel_launch(void* const* d_in, const int* in_sizes, int n_in,
                              void* d_out, int out_size)
{
    const float* points   = (const float*)d_in[0];
    const float* features = (const float*)d_in[1];
    const float* refs     = (const float*)d_in[2];
    const float* W1 = (const float*)d_in[3];
    const float* g1 = (const float*)d_in[4];
    const float* b1 = (const float*)d_in[5];
    const float* m1 = (const float*)d_in[6];
    const float* v1 = (const float*)d_in[7];
    const float* W2 = (const float*)d_in[8];
    const float* g2 = (const float*)d_in[9];
    const float* b2 = (const float*)d_in[10];
    const float* m2 = (const float*)d_in[11];
    const float* v2 = (const float*)d_in[12];
    const float* W3 = (const float*)d_in[13];
    const float* g3 = (const float*)d_in[14];
    const float* b3 = (const float*)d_in[15];
    const float* m3 = (const float*)d_in[16];
    const float* v3 = (const float*)d_in[17];
    float* out = (float*)d_out;

    cudaFuncSetAttribute(mlp12_mma_kernel, cudaFuncAttributeMaxDynamicSharedMemorySize, SB12_TOT);
    cudaFuncSetAttribute(mlp3_mma_kernel,  cudaFuncAttributeMaxDynamicSharedMemorySize, S3B_TOTAL);

    prep_kernel<<<64, 256>>>(W1, W2, W3, g1, b1, m1, v1,
                             g2, b2, m2, v2, g3, b3, m3, v3);
    ball_query_kernel<<<NREF / 8, 256>>>(points, refs);
    mlp12_mma_kernel<<<2 * NSM, 256, SB12_TOT>>>(points, features, refs);
    mlp3_mma_kernel<<<2 * NSM, 256, S3B_TOTAL>>>(out);
}